// round 2
// baseline (speedup 1.0000x reference)
#include <cuda_runtime.h>
#include <stdint.h>

#define FULL_MASK 0xFFFFFFFFu

constexpr int   L_     = 9;
constexpr float PADF   = 1e30f;
constexpr int   VOCAB  = 128000;
constexpr int   SENTI  = 1 << 30;
constexpr float INVSQ2 = 0.70710678f;   // rounds to 0x3F3504F3, same as numpy complex64 1/sqrt(2)

__global__ __launch_bounds__(256)
void beam_kernel(const float* __restrict__ y, const float* __restrict__ h,
                 float* __restrict__ out, int T, int mode)
{
    int warp = blockIdx.x * (blockDim.x >> 5) + (threadIdx.x >> 5);
    int lane = threadIdx.x & 31;
    if (warp >= T) return;

    // ---- load: lanes 0..17 hold y row, lanes 0..1 hold h ----
    float yv = 0.f;
    if (lane < 2 * L_) yv = y[(size_t)warp * (2 * L_) + lane];
    float hv = 0.f;
    if (lane < 2) hv = h[(size_t)warp * 2 + lane];
    float hr = __shfl_sync(FULL_MASK, hv, 0);
    float hi = __shfl_sync(FULL_MASK, hv, 1);
    float yr = yv;                                  // lane l (<9): Re part
    float yi = __shfl_sync(FULL_MASK, yv, lane + 9); // lane l (<9): Im part

    // ---- per-position (lane t<9): equalize, 4 distances, top-2 with index tie-break ----
    float den = hr * hr + hi * hi;
    float rr  = (yr * hr + yi * hi) / den;
    float ri  = (yi * hr - yr * hi) / den;

    float dist[4];
#pragma unroll
    for (int j = 0; j < 4; ++j) {
        float pr = (j & 1) ? -INVSQ2 : INVSQ2;
        float pi = (j & 2) ? -INVSQ2 : INVSQ2;
        float dr = rr - pr, di = ri - pi;
        dist[j] = dr * dr + di * di;
    }
    int i0 = 0; float b0 = dist[0];
#pragma unroll
    for (int j = 1; j < 4; ++j) if (dist[j] < b0) { b0 = dist[j]; i0 = j; }
    int i1 = 0; float b1 = __int_as_float(0x7f800000);
#pragma unroll
    for (int j = 0; j < 4; ++j) if (j != i0 && dist[j] < b1) { b1 = dist[j]; i1 = j; }

    unsigned long long dpair = ((unsigned long long)__float_as_uint(b1) << 32)
                             |  (unsigned long long)__float_as_uint(b0);
    int ipack = i0 | (i1 << 2);

    // ---- beam search: lane = beam, beams kept sorted ascending by (score, cand_idx) ----
    float    s    = (lane == 0) ? 0.f : PADF;
    unsigned syms = 0;

#pragma unroll
    for (int t = 0; t < L_; ++t) {
        unsigned long long dd = __shfl_sync(FULL_MASK, dpair, t);
        int ii = __shfl_sync(FULL_MASK, ipack, t);
        float d0 = __uint_as_float((unsigned)dd);
        float d1 = __uint_as_float((unsigned)(dd >> 32));
        unsigned c0 = (unsigned)(ii & 3)        << (2 * t);
        unsigned c1 = (unsigned)((ii >> 2) & 3) << (2 * t);

        // fetch reversed partner beam (for descending B list)
        unsigned long long cur = ((unsigned long long)__float_as_uint(s) << 32) | syms;
        unsigned long long oth = __shfl_xor_sync(FULL_MASK, cur, 31);
        float    sB    = __uint_as_float((unsigned)(oth >> 32));
        unsigned symsB = (unsigned)oth & 0x3FFFFu;

        // 56-bit keys: [score:32][cand_idx:6][syms:18]  (scores >= 0 -> bits monotonic)
        unsigned long long keyA =
            ((unsigned long long)__float_as_uint(s + d0) << 24)
          | ((unsigned long long)(unsigned)(2 * lane) << 18)
          | (unsigned long long)(syms | c0);
        unsigned long long keyB =
            ((unsigned long long)__float_as_uint(sB + d1) << 24)
          | ((unsigned long long)(unsigned)(2 * (lane ^ 31) + 1) << 18)
          | (unsigned long long)(symsB | c1);

        // A asc ++ B desc is bitonic: stride-32 compare keeps 32 smallest (bitonic),
        // then 5-stage bitonic merge sorts them ascending.
        unsigned long long lo = keyA < keyB ? keyA : keyB;
#pragma unroll
        for (int st = 16; st >= 1; st >>= 1) {
            unsigned long long o = __shfl_xor_sync(FULL_MASK, lo, st);
            if (lane & st) lo = (lo > o) ? lo : o;
            else           lo = (lo < o) ? lo : o;
        }
        s    = __uint_as_float((unsigned)(lo >> 24));
        syms = (unsigned)lo & 0x3FFFFu;
    }

    // ---- pack 17-bit id: sym0<<15 | sym1<<13 | ... | sym7<<1 | sym8>>1 ----
    int id = (int)((syms >> 16) & 3u) >> 1;
#pragma unroll
    for (int t = 0; t < 8; ++t)
        id |= (int)((syms >> (2 * t)) & 3u) << (15 - 2 * t);

    bool valid = (s < 0.5f * PADF) && (id < VOCAB);
    int v = valid ? id : SENTI;

    // ---- bitonic sort 32 ids ascending ----
#pragma unroll
    for (int k = 2; k <= 32; k <<= 1) {
#pragma unroll
        for (int j = k >> 1; j >= 1; j >>= 1) {
            int o = __shfl_xor_sync(FULL_MASK, v, j);
            bool asc   = ((lane & k) == 0);
            bool lower = ((lane & j) == 0);
            v = (asc == lower) ? min(v, o) : max(v, o);
        }
    }

    // ---- dedup + compact: unique valid ids first (already sorted), then -1 ----
    int  prev = __shfl_up_sync(FULL_MASK, v, 1);
    bool keep = (v != SENTI) && (lane == 0 || v != prev);
    unsigned m = __ballot_sync(FULL_MASK, keep);
    unsigned srcbit = __fns(m, 0, lane + 1);           // position of (lane+1)-th kept element
    int shv   = __shfl_sync(FULL_MASK, v, (int)(srcbit & 31));
    int outid = (srcbit == 0xFFFFFFFFu) ? -1 : shv;

    size_t base = (size_t)warp * 32 + lane;
    if (mode == 2) {
        out[base] = (float)outid;                      // ids as float32 (exact: |id| < 2^17)
        out[(size_t)T * 32 + base] = s;                // scores, beam order (ascending)
    } else {
        ((int*)out)[base] = outid;                     // ids-only int32 fallback
    }
}

extern "C" void kernel_launch(void* const* d_in, const int* in_sizes, int n_in,
                              void* d_out, int out_size)
{
    const float* y = (const float*)d_in[0];
    const float* h = (const float*)d_in[1];
    int T = in_sizes[0] / (2 * L_);                    // 131072
    int mode = (out_size >= T * 64) ? 2 : 1;           // 2: [ids|scores] concat as f32
    int warpsPerBlock = 8;
    int blocks = (T + warpsPerBlock - 1) / warpsPerBlock;
    beam_kernel<<<blocks, warpsPerBlock * 32>>>(y, h, (float*)d_out, T, mode);
}

// round 3
// speedup vs baseline: 1.2110x; 1.2110x over previous
#include <cuda_runtime.h>
#include <stdint.h>

#define FULL_MASK 0xFFFFFFFFu

constexpr int   L_     = 9;
constexpr float PADF   = 1e30f;
constexpr int   VOCAB  = 128000;
constexpr int   SENTI  = 1 << 30;
constexpr float INVSQ2 = 0.70710678f;   // 0x3F3504F3, same as numpy complex64 1/sqrt(2)

// One ascending bitonic-merge exchange at lane-stride st.
// Key: float score (>=0, PADF finite). Payload rides along. Ties: both keep own.
__device__ __forceinline__ void stage(float& key, unsigned& pay, int st, int lane)
{
    float    ok = __shfl_xor_sync(FULL_MASK, key, st);
    unsigned op = __shfl_xor_sync(FULL_MASK, pay, st);
    bool take = (lane & st) ? (ok > key) : (ok < key);
    if (take) { key = ok; pay = op; }
}

__global__ __launch_bounds__(256)
void beam_kernel(const float* __restrict__ y, const float* __restrict__ h,
                 float* __restrict__ out, int T, int mode)
{
    int warp = blockIdx.x * (blockDim.x >> 5) + (threadIdx.x >> 5);
    int lane = threadIdx.x & 31;
    if (warp >= T) return;

    // ---- load: lanes 0..17 hold y row, lanes 0..1 hold h ----
    float yv = 0.f;
    if (lane < 2 * L_) yv = y[(size_t)warp * (2 * L_) + lane];
    float hv = 0.f;
    if (lane < 2) hv = h[(size_t)warp * 2 + lane];
    float hr = __shfl_sync(FULL_MASK, hv, 0);
    float hi = __shfl_sync(FULL_MASK, hv, 1);
    float yr = yv;                                   // lane t (<9): Re
    float yi = __shfl_sync(FULL_MASK, yv, lane + 9); // lane t (<9): Im

    // ---- per-position (lane t<9): equalize, 4 QPSK distances, top-2 ----
    float den = hr * hr + hi * hi;
    float rr  = (yr * hr + yi * hi) / den;
    float ri  = (yi * hr - yr * hi) / den;

    float dist[4];
#pragma unroll
    for (int j = 0; j < 4; ++j) {
        float pr = (j & 1) ? -INVSQ2 : INVSQ2;
        float pi = (j & 2) ? -INVSQ2 : INVSQ2;
        float dr = rr - pr, di = ri - pi;
        dist[j] = dr * dr + di * di;
    }
    int i0 = 0; float b0 = dist[0];
#pragma unroll
    for (int j = 1; j < 4; ++j) if (dist[j] < b0) { b0 = dist[j]; i0 = j; }
    int i1 = 0; float b1 = __int_as_float(0x7f800000);
#pragma unroll
    for (int j = 0; j < 4; ++j) if (j != i0 && dist[j] < b1) { b1 = dist[j]; i1 = j; }

    unsigned long long dpair = ((unsigned long long)__float_as_uint(b1) << 32)
                             |  (unsigned long long)__float_as_uint(b0);
    int ipack = i0 | (i1 << 2);

    // ---- step 0: trivial (d0 <= d1 by construction) ----
    unsigned long long dd0 = __shfl_sync(FULL_MASK, dpair, 0);
    int ii0 = __shfl_sync(FULL_MASK, ipack, 0);
    float    s    = (lane == 0) ? __uint_as_float((unsigned)dd0)
                  : (lane == 1) ? __uint_as_float((unsigned)(dd0 >> 32)) : PADF;
    unsigned syms = (lane == 0) ? (unsigned)(ii0 & 3)
                  : (lane == 1) ? (unsigned)((ii0 >> 2) & 3) : 0u;

    // ---- steps 1..8: width-specialized bitonic merges, beams kept ascending ----
#pragma unroll
    for (int t = 1; t < L_; ++t) {
        unsigned long long dd = __shfl_sync(FULL_MASK, dpair, t);
        int ii = __shfl_sync(FULL_MASK, ipack, t);
        float d0 = __uint_as_float((unsigned)dd);
        float d1 = __uint_as_float((unsigned)(dd >> 32));
        unsigned c0 = (unsigned)(ii & 3)        << (2 * t);
        unsigned c1 = (unsigned)((ii >> 2) & 3) << (2 * t);

        if (t < 5) {
            // 2^t finite beams in lanes [0,W): build [A asc | B desc | PAD...], merge width 2W.
            const int W = 1 << t;
            int src = (lane < W) ? lane : (lane ^ (2 * W - 1));
            float    ss = __shfl_sync(FULL_MASK, s, src);
            unsigned sy = __shfl_sync(FULL_MASK, syms, src);
            float key; unsigned pay;
            if (lane < W)          { key = ss + d0; pay = sy | c0; }
            else if (lane < 2 * W) { key = ss + d1; pay = sy | c1; }
            else                   { key = PADF;    pay = 0u; }
#pragma unroll
            for (int st = 16; st >= 1; st >>= 1)
                if (st <= W) stage(key, pay, st, lane);
            s = key; syms = pay;
        } else {
            // full: A asc ++ B desc is bitonic(64); elementwise min keeps 32 smallest
            float    sB  = __shfl_xor_sync(FULL_MASK, s, 31);
            unsigned syB = __shfl_xor_sync(FULL_MASK, syms, 31);
            float kA = s + d0,  kB = sB + d1;
            unsigned pA = syms | c0, pB = syB | c1;
            bool takeB = kB < kA;
            float    key = takeB ? kB : kA;
            unsigned pay = takeB ? pB : pA;
#pragma unroll
            for (int st = 16; st >= 1; st >>= 1) stage(key, pay, st, lane);
            s = key; syms = pay;
        }
    }

    // ---- pack 17-bit id: sym0<<15 | sym1<<13 | ... | sym7<<1 | sym8>>1 ----
    int id = (int)((syms >> 16) & 3u) >> 1;
#pragma unroll
    for (int t = 0; t < 8; ++t)
        id |= (int)((syms >> (2 * t)) & 3u) << (15 - 2 * t);

    bool valid = (s < 0.5f * PADF) && (id < VOCAB);
    int v = valid ? id : SENTI;

    // ---- bitonic sort 32 ids ascending (IMNMX per stage) ----
#pragma unroll
    for (int k = 2; k <= 32; k <<= 1) {
#pragma unroll
        for (int j = k >> 1; j >= 1; j >>= 1) {
            int o = __shfl_xor_sync(FULL_MASK, v, j);
            bool asc   = ((lane & k) == 0);
            bool lower = ((lane & j) == 0);
            v = (asc == lower) ? min(v, o) : max(v, o);
        }
    }

    // ---- dedup + compact: unique valid ids first (already sorted), then -1 ----
    int  prev = __shfl_up_sync(FULL_MASK, v, 1);
    bool keep = (v != SENTI) && (lane == 0 || v != prev);
    unsigned m = __ballot_sync(FULL_MASK, keep);
    unsigned srcbit = __fns(m, 0, lane + 1);
    int shv   = __shfl_sync(FULL_MASK, v, (int)(srcbit & 31));
    int outid = (srcbit == 0xFFFFFFFFu) ? -1 : shv;

    size_t base = (size_t)warp * 32 + lane;
    if (mode == 2) {
        out[base] = (float)outid;               // ids as float32 (exact: |id| < 2^17)
        out[(size_t)T * 32 + base] = s;         // scores ascending
    } else {
        ((int*)out)[base] = outid;
    }
}

extern "C" void kernel_launch(void* const* d_in, const int* in_sizes, int n_in,
                              void* d_out, int out_size)
{
    const float* y = (const float*)d_in[0];
    const float* h = (const float*)d_in[1];
    int T = in_sizes[0] / (2 * L_);
    int mode = (out_size >= T * 64) ? 2 : 1;
    int warpsPerBlock = 8;
    int blocks = (T + warpsPerBlock - 1) / warpsPerBlock;
    beam_kernel<<<blocks, warpsPerBlock * 32>>>(y, h, (float*)d_out, T, mode);
}

// round 4
// speedup vs baseline: 1.6772x; 1.3850x over previous
#include <cuda_runtime.h>
#include <stdint.h>

#define FULL_MASK 0xFFFFFFFFu

constexpr int   L_     = 9;
constexpr float PADF   = 1e30f;
constexpr int   VOCAB  = 128000;
constexpr int   SENTI  = 1 << 30;
constexpr float INVSQ2 = 0.70710678f;   // 0x3F3504F3, same as numpy complex64 1/sqrt(2)

// Ascending bitonic exchange at lane-stride ST.
// Key: predicated FMNMX. Payload: moves iff key changed (ties carry identical
// payloads by construction, so "key unchanged -> keep own pay" is exact).
#define STAGE(KEY, PAY, ST) do {                                        \
    float    _ok = __shfl_xor_sync(FULL_MASK, (KEY), (ST));             \
    unsigned _op = __shfl_xor_sync(FULL_MASK, (PAY), (ST));             \
    float    _old = (KEY);                                              \
    (KEY) = (lane & (ST)) ? fmaxf(_old, _ok) : fminf(_old, _ok);        \
    if ((KEY) != _old) (PAY) = _op;                                     \
} while (0)

__global__ __launch_bounds__(256)
void beam_kernel(const float* __restrict__ y, const float* __restrict__ h,
                 float* __restrict__ out, int T, int mode)
{
    int warp = blockIdx.x * (blockDim.x >> 5) + (threadIdx.x >> 5);
    int lane = threadIdx.x & 31;
    int row0 = warp * 2;
    if (row0 >= T) return;
    int rows[2];
    rows[0] = row0;
    rows[1] = min(row0 + 1, T - 1);

    // ---- per-row front end: equalize, 4 QPSK distances, top-2 per position ----
    float dlo[2], dhi[2];
    int   ip[2];
#pragma unroll
    for (int q = 0; q < 2; ++q) {
        float yv = 0.f, hv = 0.f;
        if (lane < 2 * L_) yv = y[(size_t)rows[q] * (2 * L_) + lane];
        if (lane < 2)      hv = h[(size_t)rows[q] * 2 + lane];
        float hr = __shfl_sync(FULL_MASK, hv, 0);
        float hi = __shfl_sync(FULL_MASK, hv, 1);
        float yr = yv;                                   // lane t (<9): Re
        float yi = __shfl_sync(FULL_MASK, yv, lane + 9); // lane t (<9): Im

        float den = hr * hr + hi * hi;
        float rr  = (yr * hr + yi * hi) / den;
        float ri  = (yi * hr - yr * hi) / den;

        float dist[4];
#pragma unroll
        for (int j = 0; j < 4; ++j) {
            float pr = (j & 1) ? -INVSQ2 : INVSQ2;
            float pi = (j & 2) ? -INVSQ2 : INVSQ2;
            float dr = rr - pr, di = ri - pi;
            dist[j] = dr * dr + di * di;
        }
        int i0 = 0; float b0 = dist[0];
#pragma unroll
        for (int j = 1; j < 4; ++j) if (dist[j] < b0) { b0 = dist[j]; i0 = j; }
        int i1 = 0; float b1 = __int_as_float(0x7f800000);
#pragma unroll
        for (int j = 0; j < 4; ++j) if (j != i0 && dist[j] < b1) { b1 = dist[j]; i1 = j; }
        dlo[q] = b0; dhi[q] = b1; ip[q] = i0 | (i1 << 2);
    }

    // ---- step 0: trivial (d0 <= d1 by construction). Path accumulates MSB-first. ----
    float s[2]; unsigned pay[2];
#pragma unroll
    for (int q = 0; q < 2; ++q) {
        float d0 = __shfl_sync(FULL_MASK, dlo[q], 0);
        float d1 = __shfl_sync(FULL_MASK, dhi[q], 0);
        int   ii = __shfl_sync(FULL_MASK, ip[q], 0);
        s[q]   = (lane == 0) ? d0 : (lane == 1) ? d1 : PADF;
        pay[q] = (lane == 0) ? (unsigned)(ii & 3)
               : (lane == 1) ? (unsigned)((ii >> 2) & 3) : 0u;
    }

    // ---- steps 1..8: width-specialized bitonic merges, 2 rows interleaved for ILP ----
#pragma unroll
    for (int t = 1; t < L_; ++t) {
        float d0[2], d1[2]; unsigned c0[2], c1[2];
#pragma unroll
        for (int q = 0; q < 2; ++q) {
            d0[q] = __shfl_sync(FULL_MASK, dlo[q], t);
            d1[q] = __shfl_sync(FULL_MASK, dhi[q], t);
            int ii = __shfl_sync(FULL_MASK, ip[q], t);
            c0[q] = (unsigned)(ii & 3);
            c1[q] = (unsigned)((ii >> 2) & 3);
        }
        if (t < 5) {
            const int W = 1 << t;                 // finite beams entering this step
            int src = (lane < W) ? lane : (lane ^ (2 * W - 1));
#pragma unroll
            for (int q = 0; q < 2; ++q) {
                float    ss = __shfl_sync(FULL_MASK, s[q], src);
                unsigned sp = __shfl_sync(FULL_MASK, pay[q], src);
                float key; unsigned pp;
                if (lane < W)          { key = ss + d0[q]; pp = sp * 4u + c0[q]; }
                else if (lane < 2 * W) { key = ss + d1[q]; pp = sp * 4u + c1[q]; }
                else                   { key = PADF;       pp = 0u; }
                s[q] = key; pay[q] = pp;
            }
#pragma unroll
            for (int st = 16; st >= 1; st >>= 1) {
                if (st <= W) {
#pragma unroll
                    for (int q = 0; q < 2; ++q) STAGE(s[q], pay[q], st);
                }
            }
        } else {
            // full width: A asc ++ B desc bitonic(64); half-cleaner keeps 32 smallest
#pragma unroll
            for (int q = 0; q < 2; ++q) {
                float    sB  = __shfl_xor_sync(FULL_MASK, s[q], 31);
                unsigned pB0 = __shfl_xor_sync(FULL_MASK, pay[q], 31);
                float kA = s[q] + d0[q], kB = sB + d1[q];
                unsigned pA = pay[q] * 4u + c0[q];
                unsigned pB = pB0   * 4u + c1[q];
                bool takeB = kB < kA;
                s[q]   = takeB ? kB : kA;
                pay[q] = takeB ? pB : pA;
            }
#pragma unroll
            for (int st = 16; st >= 1; st >>= 1) {
#pragma unroll
                for (int q = 0; q < 2; ++q) STAGE(s[q], pay[q], st);
            }
        }
    }

    // ---- epilogue per row: id = pay>>1 (exact 17-bit repack), sort, dedup, compact ----
#pragma unroll
    for (int q = 0; q < 2; ++q) {
        int id = (int)(pay[q] >> 1);
        bool valid = (s[q] < 0.5f * PADF) && (id < VOCAB);
        int v = valid ? id : SENTI;

#pragma unroll
        for (int k = 2; k <= 32; k <<= 1) {
#pragma unroll
            for (int j = k >> 1; j >= 1; j >>= 1) {
                int o = __shfl_xor_sync(FULL_MASK, v, j);
                bool keepMin = (((lane & k) == 0) == ((lane & j) == 0));
                v = keepMin ? min(v, o) : max(v, o);
            }
        }

        int  prev = __shfl_up_sync(FULL_MASK, v, 1);
        bool keep = (v != SENTI) && (lane == 0 || v != prev);
        unsigned m = __ballot_sync(FULL_MASK, keep);
        unsigned srcbit = __fns(m, 0, lane + 1);
        int shv   = __shfl_sync(FULL_MASK, v, (int)(srcbit & 31));
        int outid = (srcbit == 0xFFFFFFFFu) ? -1 : shv;

        size_t base = (size_t)rows[q] * 32 + lane;
        if (mode == 2) {
            out[base] = (float)outid;           // ids as float32 (exact: |id| < 2^17)
            out[(size_t)T * 32 + base] = s[q];  // scores ascending
        } else {
            ((int*)out)[base] = outid;
        }
    }
}

extern "C" void kernel_launch(void* const* d_in, const int* in_sizes, int n_in,
                              void* d_out, int out_size)
{
    const float* y = (const float*)d_in[0];
    const float* h = (const float*)d_in[1];
    int T = in_sizes[0] / (2 * L_);
    int mode = (out_size >= T * 64) ? 2 : 1;
    int warpsPerBlock = 8;
    int nwarps = (T + 1) / 2;
    int blocks = (nwarps + warpsPerBlock - 1) / warpsPerBlock;
    beam_kernel<<<blocks, warpsPerBlock * 32>>>(y, h, (float*)d_out, T, mode);
}